// round 1
// baseline (speedup 1.0000x reference)
#include <cuda_runtime.h>
#include <stdint.h>

// Problem: x[8, 4096, 2048] fp32 -> out[10, 4096, 2048] fp32
//   out[0]   = sigmoid(x[0]) + x[0]
//   out[t]   = sigmoid(x[t]) + out[t-1]   for t = 1..7
//   out[8,9] = 0
// Pure elementwise scan over dim0; memory-bound streaming kernel.

#define PLANE_ELEMS (4096u * 2048u)          // elements per t-plane
#define PLANE_V4    (PLANE_ELEMS / 4u)       // float4 per t-plane = 2,097,152
#define T_IN        8
#define T_OUT       10

__device__ __forceinline__ float sigmoidf_fast(float x) {
    // 1 / (1 + e^{-x}); __expf is ~2ulp in reduced range, far under 1e-3 gate.
    return __fdividef(1.0f, 1.0f + __expf(-x));
}

__global__ void __launch_bounds__(128)
scan_sigmoid_kernel(const float4* __restrict__ in4, float4* __restrict__ out4) {
    const uint32_t i = blockIdx.x * blockDim.x + threadIdx.x;
    if (i >= PLANE_V4) return;

    // t = 0: carry init IS x[0], same plane as the first operand -> single load.
    float4 v0 = in4[i];
    float4 c;
    c.x = v0.x + sigmoidf_fast(v0.x);
    c.y = v0.y + sigmoidf_fast(v0.y);
    c.z = v0.z + sigmoidf_fast(v0.z);
    c.w = v0.w + sigmoidf_fast(v0.w);
    out4[i] = c;

    #pragma unroll
    for (int t = 1; t < T_IN; ++t) {
        float4 v = in4[(size_t)t * PLANE_V4 + i];
        c.x += sigmoidf_fast(v.x);
        c.y += sigmoidf_fast(v.y);
        c.z += sigmoidf_fast(v.z);
        c.w += sigmoidf_fast(v.w);
        out4[(size_t)t * PLANE_V4 + i] = c;
    }

    const float4 zero = make_float4(0.f, 0.f, 0.f, 0.f);
    out4[(size_t)8 * PLANE_V4 + i] = zero;
    out4[(size_t)9 * PLANE_V4 + i] = zero;
}

extern "C" void kernel_launch(void* const* d_in, const int* in_sizes, int n_in,
                              void* d_out, int out_size) {
    (void)in_sizes; (void)n_in; (void)out_size;
    const float4* in4 = (const float4*)d_in[0];
    float4* out4 = (float4*)d_out;

    const uint32_t threads = 128;
    const uint32_t blocks  = (PLANE_V4 + threads - 1) / threads;  // 16384
    scan_sigmoid_kernel<<<blocks, threads>>>(in4, out4);
}

// round 5
// speedup vs baseline: 1.0035x; 1.0035x over previous
#include <cuda_runtime.h>
#include <stdint.h>

// x[8, 4096, 2048] fp32 -> out[10, 4096, 2048] fp32
//   out[0] = sigmoid(x[0]) + x[0];  out[t] = sigmoid(x[t]) + out[t-1], t=1..7
//   out[8] = out[9] = 0
// Memory-bound stream: 576 MB total traffic. Strategy: max MLP (front-batch
// all 8 LDG.128 per thread) + evict-first cache hints on both streams.

#define PLANE_ELEMS (4096u * 2048u)
#define PLANE_V4    (PLANE_ELEMS / 4u)   // 2,097,152 float4 per plane
#define T_IN        8

__device__ __forceinline__ float sigmoidf_fast(float x) {
    return __fdividef(1.0f, 1.0f + __expf(-x));
}

__global__ void __launch_bounds__(256)
scan_sigmoid_kernel(const float4* __restrict__ in4, float4* __restrict__ out4) {
    const uint32_t i = blockIdx.x * blockDim.x + threadIdx.x;
    if (i >= PLANE_V4) return;

    // ---- Phase 1: front-batch all 8 plane loads (MLP = 8 per thread) ----
    float4 v[T_IN];
    #pragma unroll
    for (int t = 0; t < T_IN; ++t)
        v[t] = __ldcs(&in4[(size_t)t * PLANE_V4 + i]);

    // ---- Phase 2: in-place prefix: v[t] becomes out[t] ----
    // t=0: carry init is x[0] itself -> out[0] = x[0] + sigmoid(x[0])
    v[0].x += sigmoidf_fast(v[0].x);
    v[0].y += sigmoidf_fast(v[0].y);
    v[0].z += sigmoidf_fast(v[0].z);
    v[0].w += sigmoidf_fast(v[0].w);
    #pragma unroll
    for (int t = 1; t < T_IN; ++t) {
        v[t].x = v[t-1].x + sigmoidf_fast(v[t].x);
        v[t].y = v[t-1].y + sigmoidf_fast(v[t].y);
        v[t].z = v[t-1].z + sigmoidf_fast(v[t].z);
        v[t].w = v[t-1].w + sigmoidf_fast(v[t].w);
    }

    // ---- Phase 3: stream out all 10 planes (evict-first) ----
    #pragma unroll
    for (int t = 0; t < T_IN; ++t)
        __stcs(&out4[(size_t)t * PLANE_V4 + i], v[t]);

    const float4 zero = make_float4(0.f, 0.f, 0.f, 0.f);
    __stcs(&out4[(size_t)8 * PLANE_V4 + i], zero);
    __stcs(&out4[(size_t)9 * PLANE_V4 + i], zero);
}

extern "C" void kernel_launch(void* const* d_in, const int* in_sizes, int n_in,
                              void* d_out, int out_size) {
    (void)in_sizes; (void)n_in; (void)out_size;
    const float4* in4 = (const float4*)d_in[0];
    float4* out4 = (float4*)d_out;

    const uint32_t threads = 256;
    const uint32_t blocks  = (PLANE_V4 + threads - 1) / threads;  // 8192
    scan_sigmoid_kernel<<<blocks, threads>>>(in4, out4);
}